// round 1
// baseline (speedup 1.0000x reference)
#include <cuda_runtime.h>
#include <cstdint>
#include <cstddef>

#define B_TOT 512
#define IC    1152
#define CD    160
#define KD    8

// ---------------- scratch (device globals; no allocation at runtime) -------
__device__ float g_uhat[(size_t)B_TOT * IC * CD];  // 377 MB
__device__ float g_s1[B_TOT * CD];
__device__ float g_s2[B_TOT * CD];
__device__ float g_s3[B_TOT * CD];
__device__ float g_v1[B_TOT * CD];
__device__ float g_v2[B_TOT * CD];

// ---------------- K1: u_hat = einsum('icdk,bik->bicd') + s1 partials -------
#define BT 32          // b per block
#define IT 36          // i per block
#define CHK 18         // i per W smem chunk
#define K1_THREADS 320
#define K1_SMEM_FLOATS (BT*IT*KD + CHK*CD*KD)   // 9216 + 23040 = 32256

__global__ void __launch_bounds__(K1_THREADS, 1)
k_uhat(const float* __restrict__ u, const float* __restrict__ W) {
    extern __shared__ float sm[];
    float* u_s = sm;                  // [BT][IT][8]
    float* w_s = sm + BT * IT * KD;   // [CHK][160][8]

    const int tid = threadIdx.x;
    const int b0  = blockIdx.x * BT;
    const int i0  = blockIdx.y * IT;

    // stage u tile: u[b0+bl, i0+ii, k]
    for (int idx = tid; idx < BT * IT * KD; idx += K1_THREADS) {
        int bl = idx / (IT * KD);
        int r  = idx - bl * (IT * KD);
        u_s[idx] = u[(size_t)(b0 + bl) * (IC * KD) + (size_t)i0 * KD + r];
    }

    const int cd = tid % CD;     // 0..159
    const int bh = tid / CD;     // 0 or 1  -> which 16 b's

    float sacc[16];
#pragma unroll
    for (int x = 0; x < 16; x++) sacc[x] = 0.f;

    for (int ch = 0; ch < IT / CHK; ch++) {
        __syncthreads();   // protects u_s (first iter) and previous w_s use
        const int ibase = i0 + ch * CHK;
        for (int idx = tid; idx < CHK * CD * KD; idx += K1_THREADS)
            w_s[idx] = W[(size_t)ibase * (CD * KD) + idx];
        __syncthreads();

        for (int il = 0; il < CHK; il++) {
            const float4 wa = *(const float4*)&w_s[(il * CD + cd) * KD];
            const float4 wb = *(const float4*)&w_s[(il * CD + cd) * KD + 4];
            const int ig   = ibase + il;
            const int iloc = ch * CHK + il;
#pragma unroll
            for (int bb = 0; bb < 16; bb++) {
                const int bl = bh * 16 + bb;
                const float4 ua = *(const float4*)&u_s[(bl * IT + iloc) * KD];
                const float4 ub = *(const float4*)&u_s[(bl * IT + iloc) * KD + 4];
                float uh = wa.x * ua.x + wa.y * ua.y + wa.z * ua.z + wa.w * ua.w
                         + wb.x * ub.x + wb.y * ub.y + wb.z * ub.z + wb.w * ub.w;
                g_uhat[(size_t)((b0 + bl) * IC + ig) * CD + cd] = uh;
                sacc[bb] += uh;
            }
        }
    }
#pragma unroll
    for (int bb = 0; bb < 16; bb++)
        atomicAdd(&g_s1[(b0 + bh * 16 + bb) * CD + cd], sacc[bb]);
}

// ---------------- squash ----------------------------------------------------
__global__ void k_squash(const float* __restrict__ s, float* __restrict__ v, float scale) {
    const int idx = blockIdx.x * blockDim.x + threadIdx.x;   // (b, c)
    if (idx >= B_TOT * 10) return;
    float vals[16];
    const float4* s4 = (const float4*)(s + (size_t)idx * 16);
#pragma unroll
    for (int q = 0; q < 4; q++) {
        float4 t = s4[q];
        vals[4*q+0] = t.x * scale; vals[4*q+1] = t.y * scale;
        vals[4*q+2] = t.z * scale; vals[4*q+3] = t.w * scale;
    }
    float n2 = 0.f;
#pragma unroll
    for (int d = 0; d < 16; d++) n2 += vals[d] * vals[d];
    const float norm = sqrtf(n2);
    const float f = (n2 / (1.f + n2)) / (norm + 1e-8f);
    float4* v4 = (float4*)(v + (size_t)idx * 16);
#pragma unroll
    for (int q = 0; q < 4; q++) {
        float4 o;
        o.x = f * vals[4*q+0]; o.y = f * vals[4*q+1];
        o.z = f * vals[4*q+2]; o.w = f * vals[4*q+3];
        v4[q] = o;
    }
}

// ---------------- routing pass ---------------------------------------------
// Warp handles 4 (b,i) pairs per step. Lane = grp*8+sub. Each 8-lane group
// owns one i; lane's float4 chunks are c4 = sub + 8j (j=0..4), i.e.
// cd = 4*(sub+8j)+e. Class of chunk = 2j + (sub>=4). Agreement reduces over
// the 4-lane subgroup (xor 1,2), halves exchanged with xor 4.
__device__ __forceinline__ float ex2a(float x) { float y; asm("ex2.approx.f32 %0, %1;" : "=f"(y) : "f"(x)); return y; }
__device__ __forceinline__ float rcpa(float x) { float y; asm("rcp.approx.f32 %0, %1;" : "=f"(y) : "f"(x)); return y; }

#define NSPL 2

template <int NV>
__global__ void __launch_bounds__(256, 2)
k_route(float* __restrict__ s_out) {
    const int b      = blockIdx.x;
    const int isplit = blockIdx.y;
    const int tid  = threadIdx.x;
    const int warp = tid >> 5, lane = tid & 31;
    const int grp = lane >> 3, sub = lane & 7;
    const int odd = sub >> 2;     // 0: even classes, 1: odd classes

    const float4* v1_4 = (const float4*)g_v1;
    const float4* v2_4 = (const float4*)g_v2;
    const float4* uh_4 = (const float4*)g_uhat;

    float4 v1r[5], v2r[5];
#pragma unroll
    for (int j = 0; j < 5; j++) {
        v1r[j] = v1_4[b * 40 + sub + 8 * j];
        if (NV == 2) v2r[j] = v2_4[b * 40 + sub + 8 * j];
    }
    float4 sacc[5];
#pragma unroll
    for (int j = 0; j < 5; j++) sacc[j] = make_float4(0.f, 0.f, 0.f, 0.f);

    const int iper = IC / NSPL;          // 576
    for (int t = 0; t < iper / 32; t++) {
        const int i = isplit * iper + t * 32 + warp * 4 + grp;
        const size_t base = (size_t)(b * IC + i) * 40;
        float4 uh[5];
        float l[10];
#pragma unroll
        for (int j = 0; j < 5; j++) {
            uh[j] = uh_4[base + sub + 8 * j];
            float d = uh[j].x * v1r[j].x + uh[j].y * v1r[j].y
                    + uh[j].z * v1r[j].z + uh[j].w * v1r[j].w;
            if (NV == 2)
                d += uh[j].x * v2r[j].x + uh[j].y * v2r[j].y
                   + uh[j].z * v2r[j].z + uh[j].w * v2r[j].w;
            d += __shfl_xor_sync(0xffffffffu, d, 1);
            d += __shfl_xor_sync(0xffffffffu, d, 2);
            float o = __shfl_xor_sync(0xffffffffu, d, 4);
            if (odd) { l[2*j+1] = d; l[2*j]   = o; }
            else     { l[2*j]   = d; l[2*j+1] = o; }
        }
        // softmax over 10 classes (per (b,i); SIMT across pairs, no redundancy waste)
        float m = l[0];
#pragma unroll
        for (int c = 1; c < 10; c++) m = fmaxf(m, l[c]);
        float e[10]; float sum = 0.f;
#pragma unroll
        for (int c = 0; c < 10; c++) { e[c] = ex2a((l[c] - m) * 1.4426950408889634f); sum += e[c]; }
        const float r = rcpa(sum);
#pragma unroll
        for (int j = 0; j < 5; j++) {
            const float cw = (odd ? e[2*j+1] : e[2*j]) * r;
            sacc[j].x += cw * uh[j].x; sacc[j].y += cw * uh[j].y;
            sacc[j].z += cw * uh[j].z; sacc[j].w += cw * uh[j].w;
        }
    }
    float* so = s_out + b * CD;
#pragma unroll
    for (int j = 0; j < 5; j++) {
        const int cdb = 4 * (sub + 8 * j);
        atomicAdd(&so[cdb + 0], sacc[j].x);
        atomicAdd(&so[cdb + 1], sacc[j].y);
        atomicAdd(&so[cdb + 2], sacc[j].z);
        atomicAdd(&so[cdb + 3], sacc[j].w);
    }
}

// ---------------- launch -----------------------------------------------------
extern "C" void kernel_launch(void* const* d_in, const int* in_sizes, int n_in,
                              void* d_out, int out_size) {
    const float* u = (const float*)d_in[0];
    const float* W = (const float*)d_in[1];
    if (n_in >= 2 && in_sizes[0] == IC * 10 * 16 * KD) {  // safety: swap if order differs
        const float* t = u; u = W; W = t;
    }

    cudaFuncSetAttribute(k_uhat, cudaFuncAttributeMaxDynamicSharedMemorySize,
                         K1_SMEM_FLOATS * (int)sizeof(float));

    void *ps1, *ps2, *ps3, *pv1, *pv2;
    cudaGetSymbolAddress(&ps1, g_s1);
    cudaGetSymbolAddress(&ps2, g_s2);
    cudaGetSymbolAddress(&ps3, g_s3);
    cudaGetSymbolAddress(&pv1, g_v1);
    cudaGetSymbolAddress(&pv2, g_v2);

    cudaMemsetAsync(ps1, 0, B_TOT * CD * sizeof(float), 0);
    cudaMemsetAsync(ps2, 0, B_TOT * CD * sizeof(float), 0);
    cudaMemsetAsync(ps3, 0, B_TOT * CD * sizeof(float), 0);

    // 1) u_hat + raw sum over i  (iter-0 coupling coefficients are exactly 0.1)
    k_uhat<<<dim3(B_TOT / BT, IC / IT), K1_THREADS,
             K1_SMEM_FLOATS * sizeof(float)>>>(u, W);

    const int sq_blocks = (B_TOT * 10 + 255) / 256;
    // 2) v1 = squash(0.1 * sum)
    k_squash<<<sq_blocks, 256>>>((const float*)ps1, (float*)pv1, 0.1f);
    // 3) iter-1: logits = <uhat, v1>; s2 = sum softmax(logits)*uhat
    k_route<1><<<dim3(B_TOT, NSPL), 256>>>((float*)ps2);
    // 4) v2 = squash(s2)
    k_squash<<<sq_blocks, 256>>>((const float*)ps2, (float*)pv2, 1.0f);
    // 5) iter-2: logits = <uhat,v1> + <uhat,v2>; s3
    k_route<2><<<dim3(B_TOT, NSPL), 256>>>((float*)ps3);
    // 6) output v = squash(s3)
    k_squash<<<sq_blocks, 256>>>((const float*)ps3, (float*)d_out, 1.0f);
}

// round 2
// speedup vs baseline: 1.1435x; 1.1435x over previous
#include <cuda_runtime.h>
#include <cuda_fp16.h>
#include <cstdint>
#include <cstddef>

#define B_TOT 512
#define IC    1152
#define CD    160
#define KD    8

// ---------------- scratch (device globals; no runtime allocation) ----------
__device__ __half g_uhat[(size_t)B_TOT * IC * CD];   // 188 MB, fp16
__device__ float g_s1[B_TOT * CD];
__device__ float g_s2[B_TOT * CD];
__device__ float g_s3[B_TOT * CD];
__device__ float g_v1[B_TOT * CD];
__device__ float g_v2[B_TOT * CD];

// ---------------- K1: u_hat = einsum('icdk,bik->bicd') + s1 partials -------
// Block: 32 b  x 12 i. Thread (bh=tid&7, cdq=tid>>3): 4 b's x 4 cd's.
// W staged transposed [il][k][cd] (conflict-free 16B-stride reads),
// u staged padded (stride 100 == 4 mod 32 -> disjoint bank sets per bh).
#define BT 32
#define IT 12
#define K1_THREADS 320
#define USTRIDE 100
#define K1_SMEM_FLOATS (BT*USTRIDE + IT*KD*CD)   // 3200 + 15360 = 18560

__global__ void __launch_bounds__(K1_THREADS, 2)
k_uhat(const float* __restrict__ u, const float* __restrict__ W) {
    extern __shared__ float sm[];
    float* u_s = sm;                    // [BT][USTRIDE]
    float* w_s = sm + BT * USTRIDE;     // [IT][8][160]

    const int tid = threadIdx.x;
    const int b0  = blockIdx.x * BT;
    const int i0  = blockIdx.y * IT;

    // stage u: u[b0+bl, i0.., k] -> u_s[bl*USTRIDE + r]
    for (int idx = tid; idx < BT * IT * KD; idx += K1_THREADS) {
        int bl = idx / (IT * KD);
        int r  = idx - bl * (IT * KD);
        u_s[bl * USTRIDE + r] =
            u[(size_t)(b0 + bl) * (IC * KD) + (size_t)i0 * KD + r];
    }
    // stage W transposed: global [il][cd][k] -> smem [il][k][cd]
    for (int row = tid; row < IT * CD; row += K1_THREADS) {
        int il = row / CD, cd = row - il * CD;
        const float4 wa = *(const float4*)&W[((size_t)(i0 + il) * CD + cd) * KD];
        const float4 wb = *(const float4*)&W[((size_t)(i0 + il) * CD + cd) * KD + 4];
        float* dst = &w_s[il * (KD * CD) + cd];
        dst[0*CD] = wa.x; dst[1*CD] = wa.y; dst[2*CD] = wa.z; dst[3*CD] = wa.w;
        dst[4*CD] = wb.x; dst[5*CD] = wb.y; dst[6*CD] = wb.z; dst[7*CD] = wb.w;
    }
    __syncthreads();

    const int bh  = tid & 7;         // 4 b's: bl = bh*4+bb
    const int cdq = tid >> 3;        // 0..39 -> cd0 = 4*cdq
    const int cd0 = cdq * 4;

    float sacc[4][4];
#pragma unroll
    for (int x = 0; x < 4; x++)
#pragma unroll
        for (int y = 0; y < 4; y++) sacc[x][y] = 0.f;

#pragma unroll 1
    for (int il = 0; il < IT; il++) {
        // W regs: wv[k] = w[il][k][cd0..cd0+3]
        float4 wv[8];
#pragma unroll
        for (int k = 0; k < 8; k++)
            wv[k] = *(const float4*)&w_s[(il * KD + k) * CD + cd0];
        const int ig = i0 + il;
#pragma unroll
        for (int bb = 0; bb < 4; bb++) {
            const int bl = bh * 4 + bb;
            const float4 ua = *(const float4*)&u_s[bl * USTRIDE + il * KD];
            const float4 ub = *(const float4*)&u_s[bl * USTRIDE + il * KD + 4];
            float uh0 = wv[0].x*ua.x + wv[1].x*ua.y + wv[2].x*ua.z + wv[3].x*ua.w
                      + wv[4].x*ub.x + wv[5].x*ub.y + wv[6].x*ub.z + wv[7].x*ub.w;
            float uh1 = wv[0].y*ua.x + wv[1].y*ua.y + wv[2].y*ua.z + wv[3].y*ua.w
                      + wv[4].y*ub.x + wv[5].y*ub.y + wv[6].y*ub.z + wv[7].y*ub.w;
            float uh2 = wv[0].z*ua.x + wv[1].z*ua.y + wv[2].z*ua.z + wv[3].z*ua.w
                      + wv[4].z*ub.x + wv[5].z*ub.y + wv[6].z*ub.z + wv[7].z*ub.w;
            float uh3 = wv[0].w*ua.x + wv[1].w*ua.y + wv[2].w*ua.z + wv[3].w*ua.w
                      + wv[4].w*ub.x + wv[5].w*ub.y + wv[6].w*ub.z + wv[7].w*ub.w;
            sacc[bb][0] += uh0; sacc[bb][1] += uh1;
            sacc[bb][2] += uh2; sacc[bb][3] += uh3;
            __half2 p0 = __floats2half2_rn(uh0, uh1);
            __half2 p1 = __floats2half2_rn(uh2, uh3);
            uint2 q = make_uint2(*reinterpret_cast<unsigned*>(&p0),
                                 *reinterpret_cast<unsigned*>(&p1));
            *reinterpret_cast<uint2*>(
                &g_uhat[((size_t)(b0 + bl) * IC + ig) * CD + cd0]) = q;
        }
    }
#pragma unroll
    for (int bb = 0; bb < 4; bb++)
#pragma unroll
        for (int c = 0; c < 4; c++)
            atomicAdd(&g_s1[(b0 + bh * 4 + bb) * CD + cd0 + c], sacc[bb][c]);
}

// ---------------- squash ----------------------------------------------------
__global__ void k_squash(const float* __restrict__ s, float* __restrict__ v, float scale) {
    const int idx = blockIdx.x * blockDim.x + threadIdx.x;   // (b, c)
    if (idx >= B_TOT * 10) return;
    float vals[16];
    const float4* s4 = (const float4*)(s + (size_t)idx * 16);
#pragma unroll
    for (int q = 0; q < 4; q++) {
        float4 t = s4[q];
        vals[4*q+0] = t.x * scale; vals[4*q+1] = t.y * scale;
        vals[4*q+2] = t.z * scale; vals[4*q+3] = t.w * scale;
    }
    float n2 = 0.f;
#pragma unroll
    for (int d = 0; d < 16; d++) n2 += vals[d] * vals[d];
    const float norm = sqrtf(n2);
    const float f = (n2 / (1.f + n2)) / (norm + 1e-8f);
    float4* v4 = (float4*)(v + (size_t)idx * 16);
#pragma unroll
    for (int q = 0; q < 4; q++) {
        float4 o;
        o.x = f * vals[4*q+0]; o.y = f * vals[4*q+1];
        o.z = f * vals[4*q+2]; o.w = f * vals[4*q+3];
        v4[q] = o;
    }
}

// ---------------- routing pass (fp16 u_hat) ---------------------------------
__device__ __forceinline__ float ex2a(float x) { float y; asm("ex2.approx.f32 %0, %1;" : "=f"(y) : "f"(x)); return y; }
__device__ __forceinline__ float rcpa(float x) { float y; asm("rcp.approx.f32 %0, %1;" : "=f"(y) : "f"(x)); return y; }

#define NSPL 4
#define RT_THREADS 128

template <int NV>
__global__ void __launch_bounds__(RT_THREADS)
k_route(float* __restrict__ s_out) {
    const int b      = blockIdx.x;
    const int isplit = blockIdx.y;
    const int tid  = threadIdx.x;
    const int warp = tid >> 5, lane = tid & 31;
    const int grp = lane >> 3, sub = lane & 7;
    const int odd = sub >> 2;

    const float4* v1_4 = (const float4*)g_v1;
    const float4* v2_4 = (const float4*)g_v2;
    const uint2*  uh_2 = (const uint2*)g_uhat;   // 4 halves per uint2

    float4 v1r[5], v2r[5];
#pragma unroll
    for (int j = 0; j < 5; j++) {
        v1r[j] = v1_4[b * 40 + sub + 8 * j];
        if (NV == 2) v2r[j] = v2_4[b * 40 + sub + 8 * j];
    }
    float4 sacc[5];
#pragma unroll
    for (int j = 0; j < 5; j++) sacc[j] = make_float4(0.f, 0.f, 0.f, 0.f);

    const int iper = IC / NSPL;          // 288
#pragma unroll 2
    for (int t = 0; t < iper / 16; t++) {
        const int i = isplit * iper + t * 16 + warp * 4 + grp;
        const size_t base = (size_t)(b * IC + i) * 40;
        float4 uh[5];
        float l[10];
#pragma unroll
        for (int j = 0; j < 5; j++) {
            uint2 q = uh_2[base + sub + 8 * j];
            __half2 h0 = *reinterpret_cast<const __half2*>(&q.x);
            __half2 h1 = *reinterpret_cast<const __half2*>(&q.y);
            float2 f0 = __half22float2(h0);
            float2 f1 = __half22float2(h1);
            uh[j] = make_float4(f0.x, f0.y, f1.x, f1.y);
            float d = uh[j].x * v1r[j].x + uh[j].y * v1r[j].y
                    + uh[j].z * v1r[j].z + uh[j].w * v1r[j].w;
            if (NV == 2)
                d += uh[j].x * v2r[j].x + uh[j].y * v2r[j].y
                   + uh[j].z * v2r[j].z + uh[j].w * v2r[j].w;
            d += __shfl_xor_sync(0xffffffffu, d, 1);
            d += __shfl_xor_sync(0xffffffffu, d, 2);
            float o = __shfl_xor_sync(0xffffffffu, d, 4);
            if (odd) { l[2*j+1] = d; l[2*j]   = o; }
            else     { l[2*j]   = d; l[2*j+1] = o; }
        }
        float m = l[0];
#pragma unroll
        for (int c = 1; c < 10; c++) m = fmaxf(m, l[c]);
        float e[10]; float sum = 0.f;
#pragma unroll
        for (int c = 0; c < 10; c++) { e[c] = ex2a((l[c] - m) * 1.4426950408889634f); sum += e[c]; }
        const float r = rcpa(sum);
#pragma unroll
        for (int j = 0; j < 5; j++) {
            const float cw = (odd ? e[2*j+1] : e[2*j]) * r;
            sacc[j].x += cw * uh[j].x; sacc[j].y += cw * uh[j].y;
            sacc[j].z += cw * uh[j].z; sacc[j].w += cw * uh[j].w;
        }
    }
    float* so = s_out + b * CD;
#pragma unroll
    for (int j = 0; j < 5; j++) {
        const int cdb = 4 * (sub + 8 * j);
        atomicAdd(&so[cdb + 0], sacc[j].x);
        atomicAdd(&so[cdb + 1], sacc[j].y);
        atomicAdd(&so[cdb + 2], sacc[j].z);
        atomicAdd(&so[cdb + 3], sacc[j].w);
    }
}

// ---------------- launch -----------------------------------------------------
extern "C" void kernel_launch(void* const* d_in, const int* in_sizes, int n_in,
                              void* d_out, int out_size) {
    const float* u = (const float*)d_in[0];
    const float* W = (const float*)d_in[1];
    if (n_in >= 2 && in_sizes[0] == IC * CD * KD) {  // safety: swap if order differs
        const float* t = u; u = W; W = t;
    }

    cudaFuncSetAttribute(k_uhat, cudaFuncAttributeMaxDynamicSharedMemorySize,
                         K1_SMEM_FLOATS * (int)sizeof(float));

    void *ps1, *ps2, *ps3, *pv1, *pv2;
    cudaGetSymbolAddress(&ps1, g_s1);
    cudaGetSymbolAddress(&ps2, g_s2);
    cudaGetSymbolAddress(&ps3, g_s3);
    cudaGetSymbolAddress(&pv1, g_v1);
    cudaGetSymbolAddress(&pv2, g_v2);

    cudaMemsetAsync(ps1, 0, B_TOT * CD * sizeof(float), 0);
    cudaMemsetAsync(ps2, 0, B_TOT * CD * sizeof(float), 0);
    cudaMemsetAsync(ps3, 0, B_TOT * CD * sizeof(float), 0);

    // 1) u_hat (fp16) + raw sum over i (iter-0 coupling coeffs are exactly 0.1)
    k_uhat<<<dim3(B_TOT / BT, IC / IT), K1_THREADS,
             K1_SMEM_FLOATS * sizeof(float)>>>(u, W);

    const int sq_blocks = (B_TOT * 10 + 255) / 256;
    // 2) v1 = squash(0.1 * sum)
    k_squash<<<sq_blocks, 256>>>((const float*)ps1, (float*)pv1, 0.1f);
    // 3) iter-1: logits = <uhat, v1>; s2
    k_route<1><<<dim3(B_TOT, NSPL), RT_THREADS>>>((float*)ps2);
    // 4) v2 = squash(s2)
    k_squash<<<sq_blocks, 256>>>((const float*)ps2, (float*)pv2, 1.0f);
    // 5) iter-2: logits = <uhat,v1> + <uhat,v2>; s3
    k_route<2><<<dim3(B_TOT, NSPL), RT_THREADS>>>((float*)ps3);
    // 6) output v = squash(s3)
    k_squash<<<sq_blocks, 256>>>((const float*)ps3, (float*)d_out, 1.0f);
}

// round 3
// speedup vs baseline: 1.4194x; 1.2413x over previous
#include <cuda_runtime.h>
#include <cuda_fp16.h>
#include <cstdint>
#include <cstddef>

#define B_TOT 512
#define IC    1152
#define CD    160
#define KD    8

// ---------------- scratch (device globals; no runtime allocation) ----------
__device__ __half g_uhat[(size_t)B_TOT * IC * CD];   // 188 MB, fp16
__device__ float g_s1[B_TOT * CD];
__device__ float g_s2[B_TOT * CD];
__device__ float g_s3[B_TOT * CD];

// ---------------- K1: u_hat = einsum('icdk,bik->bicd') + s1 partials -------
// Block: 32 b x 12 i. Thread (bh=tid&7, cdq=tid>>3): 4 b's x 4 cd's.
// bl = bb*8 + bh  ->  lane-adjacent rows; row stride 100 words == 4 mod 32
// -> 8 lanes' float4 reads start at banks {0,4,...,28}: conflict-free.
#define BT 32
#define IT 12
#define K1_THREADS 320
#define USTRIDE 100
#define K1_SMEM_FLOATS (BT*USTRIDE + IT*KD*CD)   // 3200 + 15360 = 18560

__global__ void __launch_bounds__(K1_THREADS, 2)
k_uhat(const float* __restrict__ u, const float* __restrict__ W) {
    extern __shared__ float sm[];
    float* u_s = sm;                    // [BT][USTRIDE]
    float* w_s = sm + BT * USTRIDE;     // [IT][8][160]

    const int tid = threadIdx.x;
    const int b0  = blockIdx.x * BT;
    const int i0  = blockIdx.y * IT;

    // stage u: u[b0+bl, i0.., k] -> u_s[bl*USTRIDE + r]
    for (int idx = tid; idx < BT * IT * KD; idx += K1_THREADS) {
        int bl = idx / (IT * KD);
        int r  = idx - bl * (IT * KD);
        u_s[bl * USTRIDE + r] =
            u[(size_t)(b0 + bl) * (IC * KD) + (size_t)i0 * KD + r];
    }
    // stage W transposed: global [il][cd][k] -> smem [il][k][cd]
    for (int row = tid; row < IT * CD; row += K1_THREADS) {
        int il = row / CD, cd = row - il * CD;
        const float4 wa = *(const float4*)&W[((size_t)(i0 + il) * CD + cd) * KD];
        const float4 wb = *(const float4*)&W[((size_t)(i0 + il) * CD + cd) * KD + 4];
        float* dst = &w_s[il * (KD * CD) + cd];
        dst[0*CD] = wa.x; dst[1*CD] = wa.y; dst[2*CD] = wa.z; dst[3*CD] = wa.w;
        dst[4*CD] = wb.x; dst[5*CD] = wb.y; dst[6*CD] = wb.z; dst[7*CD] = wb.w;
    }
    __syncthreads();

    const int bh  = tid & 7;         // row within octet
    const int cdq = tid >> 3;        // 0..39 -> cd0 = 4*cdq
    const int cd0 = cdq * 4;

    float sacc[4][4];
#pragma unroll
    for (int x = 0; x < 4; x++)
#pragma unroll
        for (int y = 0; y < 4; y++) sacc[x][y] = 0.f;

#pragma unroll 1
    for (int il = 0; il < IT; il++) {
        // W regs: wv[k] = w[il][k][cd0..cd0+3] (4 distinct addrs/warp, broadcast)
        float4 wv[8];
#pragma unroll
        for (int k = 0; k < 8; k++)
            wv[k] = *(const float4*)&w_s[(il * KD + k) * CD + cd0];
        const int ig = i0 + il;
#pragma unroll
        for (int bb = 0; bb < 4; bb++) {
            const int bl = bb * 8 + bh;          // conflict-free mapping
            const float4 ua = *(const float4*)&u_s[bl * USTRIDE + il * KD];
            const float4 ub = *(const float4*)&u_s[bl * USTRIDE + il * KD + 4];
            float uh0 = wv[0].x*ua.x + wv[1].x*ua.y + wv[2].x*ua.z + wv[3].x*ua.w
                      + wv[4].x*ub.x + wv[5].x*ub.y + wv[6].x*ub.z + wv[7].x*ub.w;
            float uh1 = wv[0].y*ua.x + wv[1].y*ua.y + wv[2].y*ua.z + wv[3].y*ua.w
                      + wv[4].y*ub.x + wv[5].y*ub.y + wv[6].y*ub.z + wv[7].y*ub.w;
            float uh2 = wv[0].z*ua.x + wv[1].z*ua.y + wv[2].z*ua.z + wv[3].z*ua.w
                      + wv[4].z*ub.x + wv[5].z*ub.y + wv[6].z*ub.z + wv[7].z*ub.w;
            float uh3 = wv[0].w*ua.x + wv[1].w*ua.y + wv[2].w*ua.z + wv[3].w*ua.w
                      + wv[4].w*ub.x + wv[5].w*ub.y + wv[6].w*ub.z + wv[7].w*ub.w;
            sacc[bb][0] += uh0; sacc[bb][1] += uh1;
            sacc[bb][2] += uh2; sacc[bb][3] += uh3;
            __half2 p0 = __floats2half2_rn(uh0, uh1);
            __half2 p1 = __floats2half2_rn(uh2, uh3);
            uint2 q = make_uint2(*reinterpret_cast<unsigned*>(&p0),
                                 *reinterpret_cast<unsigned*>(&p1));
            *reinterpret_cast<uint2*>(
                &g_uhat[((size_t)(b0 + bl) * IC + ig) * CD + cd0]) = q;
        }
    }
#pragma unroll
    for (int bb = 0; bb < 4; bb++)
#pragma unroll
        for (int c = 0; c < 4; c++)
            atomicAdd(&g_s1[(b0 + bb * 8 + bh) * CD + cd0 + c], sacc[bb][c]);
}

// ---------------- squash (final output only) --------------------------------
__global__ void k_squash(const float* __restrict__ s, float* __restrict__ v, float scale) {
    const int idx = blockIdx.x * blockDim.x + threadIdx.x;   // (b, c)
    if (idx >= B_TOT * 10) return;
    float vals[16];
    const float4* s4 = (const float4*)(s + (size_t)idx * 16);
#pragma unroll
    for (int q = 0; q < 4; q++) {
        float4 t = s4[q];
        vals[4*q+0] = t.x * scale; vals[4*q+1] = t.y * scale;
        vals[4*q+2] = t.z * scale; vals[4*q+3] = t.w * scale;
    }
    float n2 = 0.f;
#pragma unroll
    for (int d = 0; d < 16; d++) n2 += vals[d] * vals[d];
    const float norm = sqrtf(n2);
    const float f = (n2 / (1.f + n2)) / (norm + 1e-8f);
    float4* v4 = (float4*)(v + (size_t)idx * 16);
#pragma unroll
    for (int q = 0; q < 4; q++) {
        float4 o;
        o.x = f * vals[4*q+0]; o.y = f * vals[4*q+1];
        o.z = f * vals[4*q+2]; o.w = f * vals[4*q+3];
        v4[q] = o;
    }
}

// ---------------- routing pass (fp16 u_hat, fused v=squash(s) prologue) -----
__device__ __forceinline__ float ex2a(float x) { float y; asm("ex2.approx.f32 %0, %1;" : "=f"(y) : "f"(x)); return y; }
__device__ __forceinline__ float rcpa(float x) { float y; asm("rcp.approx.f32 %0, %1;" : "=f"(y) : "f"(x)); return y; }

#define NSPL 4
#define RT_THREADS 128

template <int NV>
__global__ void __launch_bounds__(RT_THREADS)
k_route(const float* __restrict__ s_a, float a_scale,
        const float* __restrict__ s_b,
        float* __restrict__ s_out) {
    __shared__ float4 v1s[40];
    __shared__ float4 v2s[40];

    const int b      = blockIdx.x;
    const int isplit = blockIdx.y;
    const int tid  = threadIdx.x;
    const int warp = tid >> 5, lane = tid & 31;
    const int grp = lane >> 3, sub = lane & 7;
    const int odd = sub >> 2;

    // fused squash: v = squash(scale * s) for this b (10 capsules)
    {
        const int cap = tid & 15;
        const int which = tid >> 4;          // 0 -> v1, 1 -> v2
        if (cap < 10 && which < (NV == 2 ? 2 : 1)) {
            const float* sp = (which == 0) ? s_a : s_b;
            const float sc = (which == 0) ? a_scale : 1.0f;
            float vals[16]; float n2 = 0.f;
#pragma unroll
            for (int d = 0; d < 16; d++) {
                vals[d] = sp[b * CD + cap * 16 + d] * sc;
                n2 += vals[d] * vals[d];
            }
            const float f = (n2 / (1.f + n2)) / (sqrtf(n2) + 1e-8f);
            float4* dst = (which == 0) ? &v1s[cap * 4] : &v2s[cap * 4];
#pragma unroll
            for (int q = 0; q < 4; q++)
                dst[q] = make_float4(f*vals[4*q], f*vals[4*q+1],
                                     f*vals[4*q+2], f*vals[4*q+3]);
        }
    }
    __syncthreads();

    const uint2* uh_2 = (const uint2*)g_uhat;   // 4 halves per uint2

    float4 v1r[5], v2r[5];
#pragma unroll
    for (int j = 0; j < 5; j++) {
        v1r[j] = v1s[sub + 8 * j];
        if (NV == 2) v2r[j] = v2s[sub + 8 * j];
    }
    float4 sacc[5];
#pragma unroll
    for (int j = 0; j < 5; j++) sacc[j] = make_float4(0.f, 0.f, 0.f, 0.f);

    const int iper = IC / NSPL;          // 288
#pragma unroll 2
    for (int t = 0; t < iper / 16; t++) {
        const int i = isplit * iper + t * 16 + warp * 4 + grp;
        const size_t base = (size_t)(b * IC + i) * 40;
        float4 uh[5];
        float l[10];
#pragma unroll
        for (int j = 0; j < 5; j++) {
            uint2 q = uh_2[base + sub + 8 * j];
            __half2 h0 = *reinterpret_cast<const __half2*>(&q.x);
            __half2 h1 = *reinterpret_cast<const __half2*>(&q.y);
            float2 f0 = __half22float2(h0);
            float2 f1 = __half22float2(h1);
            uh[j] = make_float4(f0.x, f0.y, f1.x, f1.y);
            float d = uh[j].x * v1r[j].x + uh[j].y * v1r[j].y
                    + uh[j].z * v1r[j].z + uh[j].w * v1r[j].w;
            if (NV == 2)
                d += uh[j].x * v2r[j].x + uh[j].y * v2r[j].y
                   + uh[j].z * v2r[j].z + uh[j].w * v2r[j].w;
            d += __shfl_xor_sync(0xffffffffu, d, 1);
            d += __shfl_xor_sync(0xffffffffu, d, 2);
            float o = __shfl_xor_sync(0xffffffffu, d, 4);
            if (odd) { l[2*j+1] = d; l[2*j]   = o; }
            else     { l[2*j]   = d; l[2*j+1] = o; }
        }
        float m = l[0];
#pragma unroll
        for (int c = 1; c < 10; c++) m = fmaxf(m, l[c]);
        float e[10]; float sum = 0.f;
#pragma unroll
        for (int c = 0; c < 10; c++) { e[c] = ex2a((l[c] - m) * 1.4426950408889634f); sum += e[c]; }
        const float r = rcpa(sum);
#pragma unroll
        for (int j = 0; j < 5; j++) {
            const float cw = (odd ? e[2*j+1] : e[2*j]) * r;
            sacc[j].x += cw * uh[j].x; sacc[j].y += cw * uh[j].y;
            sacc[j].z += cw * uh[j].z; sacc[j].w += cw * uh[j].w;
        }
    }
    float* so = s_out + b * CD;
#pragma unroll
    for (int j = 0; j < 5; j++) {
        const int cdb = 4 * (sub + 8 * j);
        atomicAdd(&so[cdb + 0], sacc[j].x);
        atomicAdd(&so[cdb + 1], sacc[j].y);
        atomicAdd(&so[cdb + 2], sacc[j].z);
        atomicAdd(&so[cdb + 3], sacc[j].w);
    }
}

// ---------------- launch -----------------------------------------------------
extern "C" void kernel_launch(void* const* d_in, const int* in_sizes, int n_in,
                              void* d_out, int out_size) {
    const float* u = (const float*)d_in[0];
    const float* W = (const float*)d_in[1];
    if (n_in >= 2 && in_sizes[0] == IC * CD * KD) {  // safety: swap if order differs
        const float* t = u; u = W; W = t;
    }

    cudaFuncSetAttribute(k_uhat, cudaFuncAttributeMaxDynamicSharedMemorySize,
                         K1_SMEM_FLOATS * (int)sizeof(float));

    void *ps1, *ps2, *ps3;
    cudaGetSymbolAddress(&ps1, g_s1);
    cudaGetSymbolAddress(&ps2, g_s2);
    cudaGetSymbolAddress(&ps3, g_s3);

    cudaMemsetAsync(ps1, 0, B_TOT * CD * sizeof(float), 0);
    cudaMemsetAsync(ps2, 0, B_TOT * CD * sizeof(float), 0);
    cudaMemsetAsync(ps3, 0, B_TOT * CD * sizeof(float), 0);

    // 1) u_hat (fp16) + raw sum over i (iter-0 coupling coeffs are exactly 0.1)
    k_uhat<<<dim3(B_TOT / BT, IC / IT), K1_THREADS,
             K1_SMEM_FLOATS * sizeof(float)>>>(u, W);

    // 2) iter-1: v1 = squash(0.1*s1) fused; logits = <uhat, v1>; s2
    k_route<1><<<dim3(B_TOT, NSPL), RT_THREADS>>>(
        (const float*)ps1, 0.1f, (const float*)ps1, (float*)ps2);
    // 3) iter-2: v1, v2 fused; logits = <uhat,v1> + <uhat,v2>; s3
    k_route<2><<<dim3(B_TOT, NSPL), RT_THREADS>>>(
        (const float*)ps1, 0.1f, (const float*)ps2, (float*)ps3);
    // 4) output v = squash(s3)
    const int sq_blocks = (B_TOT * 10 + 255) / 256;
    k_squash<<<sq_blocks, 256>>>((const float*)ps3, (float*)d_out, 1.0f);
}

// round 5
// speedup vs baseline: 1.5273x; 1.0760x over previous
#include <cuda_runtime.h>
#include <cuda_fp16.h>
#include <cstdint>
#include <cstddef>

#define B_TOT 512
#define IC    1152
#define CD    160
#define KD    8

// ---------------- scratch (device globals; no runtime allocation) ----------
__device__ __half g_uhat[(size_t)B_TOT * IC * CD];   // 188 MB, fp16
__device__ float  g_s[3 * B_TOT * CD];               // s1 | s2 | s3

// ---------------- f32x2 packed-math helpers (sm_103a) ----------------------
typedef unsigned long long ull;
__device__ __forceinline__ ull pack2(float lo, float hi) {
    ull r; asm("mov.b64 %0, {%1, %2};" : "=l"(r) : "f"(lo), "f"(hi)); return r;
}
__device__ __forceinline__ void unpack2(ull p, float& lo, float& hi) {
    asm("mov.b64 {%0, %1}, %2;" : "=f"(lo), "=f"(hi) : "l"(p));
}
__device__ __forceinline__ ull fma2(ull a, ull b, ull c) {
    ull d; asm("fma.rn.f32x2 %0, %1, %2, %3;" : "=l"(d) : "l"(a), "l"(b), "l"(c)); return d;
}
__device__ __forceinline__ ull add2(ull a, ull b) {
    ull d; asm("add.rn.f32x2 %0, %1, %2;" : "=l"(d) : "l"(a), "l"(b)); return d;
}

// ---------------- K1: u_hat = einsum('icdk,bik->bicd') + s1 partials -------
#define BT 32
#define IT 12
#define K1_THREADS 320
#define USTRIDE 100
#define K1_SMEM_FLOATS (BT*USTRIDE + IT*KD*CD)   // 18560 floats = 74.2 KB

__global__ void __launch_bounds__(K1_THREADS, 2)
k_uhat(const float* __restrict__ u, const float* __restrict__ W) {
    extern __shared__ float sm[];
    float* u_s = sm;                    // [BT][USTRIDE]
    float* w_s = sm + BT * USTRIDE;     // [IT][8][160]

    const int tid = threadIdx.x;
    const int b0  = blockIdx.x * BT;
    const int i0  = blockIdx.y * IT;

    for (int idx = tid; idx < BT * IT * KD; idx += K1_THREADS) {
        int bl = idx / (IT * KD);
        int r  = idx - bl * (IT * KD);
        u_s[bl * USTRIDE + r] =
            u[(size_t)(b0 + bl) * (IC * KD) + (size_t)i0 * KD + r];
    }
    for (int row = tid; row < IT * CD; row += K1_THREADS) {
        int il = row / CD, cd = row - il * CD;
        const float4 wa = *(const float4*)&W[((size_t)(i0 + il) * CD + cd) * KD];
        const float4 wb = *(const float4*)&W[((size_t)(i0 + il) * CD + cd) * KD + 4];
        float* dst = &w_s[il * (KD * CD) + cd];
        dst[0*CD] = wa.x; dst[1*CD] = wa.y; dst[2*CD] = wa.z; dst[3*CD] = wa.w;
        dst[4*CD] = wb.x; dst[5*CD] = wb.y; dst[6*CD] = wb.z; dst[7*CD] = wb.w;
    }
    __syncthreads();

    const int bh  = tid & 7;
    const int cdq = tid >> 3;
    const int cd0 = cdq * 4;

    ull sacc01[4], sacc23[4];
#pragma unroll
    for (int x = 0; x < 4; x++) { sacc01[x] = 0ull; sacc23[x] = 0ull; }

#pragma unroll 1
    for (int il = 0; il < IT; il++) {
        ull wlo[8], whi[8];
#pragma unroll
        for (int k = 0; k < 8; k++) {
            const float4 wv = *(const float4*)&w_s[(il * KD + k) * CD + cd0];
            wlo[k] = pack2(wv.x, wv.y);
            whi[k] = pack2(wv.z, wv.w);
        }
        const int ig = i0 + il;
#pragma unroll
        for (int bb = 0; bb < 4; bb++) {
            const int bl = bb * 8 + bh;
            const float4 ua = *(const float4*)&u_s[bl * USTRIDE + il * KD];
            const float4 ub = *(const float4*)&u_s[bl * USTRIDE + il * KD + 4];
            ull a01 = 0ull, a23 = 0ull, p;
            p = pack2(ua.x, ua.x); a01 = fma2(wlo[0], p, a01); a23 = fma2(whi[0], p, a23);
            p = pack2(ua.y, ua.y); a01 = fma2(wlo[1], p, a01); a23 = fma2(whi[1], p, a23);
            p = pack2(ua.z, ua.z); a01 = fma2(wlo[2], p, a01); a23 = fma2(whi[2], p, a23);
            p = pack2(ua.w, ua.w); a01 = fma2(wlo[3], p, a01); a23 = fma2(whi[3], p, a23);
            p = pack2(ub.x, ub.x); a01 = fma2(wlo[4], p, a01); a23 = fma2(whi[4], p, a23);
            p = pack2(ub.y, ub.y); a01 = fma2(wlo[5], p, a01); a23 = fma2(whi[5], p, a23);
            p = pack2(ub.z, ub.z); a01 = fma2(wlo[6], p, a01); a23 = fma2(whi[6], p, a23);
            p = pack2(ub.w, ub.w); a01 = fma2(wlo[7], p, a01); a23 = fma2(whi[7], p, a23);
            sacc01[bb] = add2(sacc01[bb], a01);
            sacc23[bb] = add2(sacc23[bb], a23);
            float f0, f1, f2, f3;
            unpack2(a01, f0, f1); unpack2(a23, f2, f3);
            __half2 pa = __floats2half2_rn(f0, f1);
            __half2 pb = __floats2half2_rn(f2, f3);
            ull payload = ((ull)*reinterpret_cast<unsigned*>(&pb) << 32)
                        |  (ull)*reinterpret_cast<unsigned*>(&pa);
            __half* dst = &g_uhat[((size_t)(b0 + bl) * IC + ig) * CD + cd0];
            asm volatile("st.global.cs.b64 [%0], %1;" :: "l"(dst), "l"(payload) : "memory");
        }
    }
#pragma unroll
    for (int bb = 0; bb < 4; bb++) {
        float f0, f1, f2, f3;
        unpack2(sacc01[bb], f0, f1); unpack2(sacc23[bb], f2, f3);
        float* so = &g_s[(b0 + bb * 8 + bh) * CD + cd0];
        atomicAdd(&so[0], f0); atomicAdd(&so[1], f1);
        atomicAdd(&so[2], f2); atomicAdd(&so[3], f3);
    }
}

// ---------------- squash (final output only) --------------------------------
__global__ void k_squash(const float* __restrict__ s, float* __restrict__ v, float scale) {
    const int idx = blockIdx.x * blockDim.x + threadIdx.x;   // (b, c)
    if (idx >= B_TOT * 10) return;
    float vals[16];
    const float4* s4 = (const float4*)(s + (size_t)idx * 16);
#pragma unroll
    for (int q = 0; q < 4; q++) {
        float4 t = s4[q];
        vals[4*q+0] = t.x * scale; vals[4*q+1] = t.y * scale;
        vals[4*q+2] = t.z * scale; vals[4*q+3] = t.w * scale;
    }
    float n2 = 0.f;
#pragma unroll
    for (int d = 0; d < 16; d++) n2 += vals[d] * vals[d];
    const float f = (n2 / (1.f + n2)) / (sqrtf(n2) + 1e-8f);
    float4* v4 = (float4*)(v + (size_t)idx * 16);
#pragma unroll
    for (int q = 0; q < 4; q++)
        v4[q] = make_float4(f*vals[4*q], f*vals[4*q+1], f*vals[4*q+2], f*vals[4*q+3]);
}

// ---------------- routing pass (fp16 u_hat, slim softmax) -------------------
__device__ __forceinline__ float ex2a(float x) { float y; asm("ex2.approx.f32 %0, %1;" : "=f"(y) : "f"(x)); return y; }
__device__ __forceinline__ float rcpa(float x) { float y; asm("rcp.approx.f32 %0, %1;" : "=f"(y) : "f"(x)); return y; }

#define NSPL 4
#define RT_THREADS 256

template <int NV>
__global__ void __launch_bounds__(RT_THREADS)
k_route(const float* __restrict__ s_a, float a_scale,
        const float* __restrict__ s_b,
        float* __restrict__ s_out) {
    __shared__ float4 vcs[40];   // combined logit vector: v1 (NV1) or v1+v2 (NV2)

    const int b      = blockIdx.x;
    const int isplit = blockIdx.y;
    const int tid  = threadIdx.x;
    const int warp = tid >> 5, lane = tid & 31;
    const int grp = lane >> 3, sub = lane & 7;

    if (tid < 10) {
        float va[16]; float n2a = 0.f;
#pragma unroll
        for (int d = 0; d < 16; d++) {
            va[d] = s_a[b * CD + tid * 16 + d] * a_scale;
            n2a += va[d] * va[d];
        }
        const float fa = (n2a / (1.f + n2a)) / (sqrtf(n2a) + 1e-8f);
        float vc[16];
#pragma unroll
        for (int d = 0; d < 16; d++) vc[d] = fa * va[d];
        if (NV == 2) {
            float vb[16]; float n2b = 0.f;
#pragma unroll
            for (int d = 0; d < 16; d++) {
                vb[d] = s_b[b * CD + tid * 16 + d];
                n2b += vb[d] * vb[d];
            }
            const float fb = (n2b / (1.f + n2b)) / (sqrtf(n2b) + 1e-8f);
#pragma unroll
            for (int d = 0; d < 16; d++) vc[d] += fb * vb[d];
        }
#pragma unroll
        for (int q = 0; q < 4; q++)
            vcs[tid * 4 + q] = make_float4(vc[4*q], vc[4*q+1], vc[4*q+2], vc[4*q+3]);
    }
    __syncthreads();

    const uint2* uh_2 = (const uint2*)g_uhat;

    float4 vr[5];
#pragma unroll
    for (int j = 0; j < 5; j++) vr[j] = vcs[sub + 8 * j];

    float4 sacc[5];
#pragma unroll
    for (int j = 0; j < 5; j++) sacc[j] = make_float4(0.f, 0.f, 0.f, 0.f);

    const int iper = IC / NSPL;          // 288;  9 rounds of 32 i
#pragma unroll 3
    for (int t = 0; t < iper / 32; t++) {
        const int i = isplit * iper + t * 32 + warp * 4 + grp;
        const size_t base = (size_t)(b * IC + i) * 40;
        uint2 q[5];
#pragma unroll
        for (int j = 0; j < 5; j++) q[j] = __ldcs(&uh_2[base + sub + 8 * j]);
        float4 uh[5];
        float e[5]; float esum = 0.f;
#pragma unroll
        for (int j = 0; j < 5; j++) {
            float2 f0 = __half22float2(*reinterpret_cast<const __half2*>(&q[j].x));
            float2 f1 = __half22float2(*reinterpret_cast<const __half2*>(&q[j].y));
            uh[j] = make_float4(f0.x, f0.y, f1.x, f1.y);
            float d = uh[j].x * vr[j].x + uh[j].y * vr[j].y
                    + uh[j].z * vr[j].z + uh[j].w * vr[j].w;
            d += __shfl_xor_sync(0xffffffffu, d, 1);
            d += __shfl_xor_sync(0xffffffffu, d, 2);
            // d = full logit for class (2j + odd); no max-sub (|logit| << 1)
            e[j] = ex2a(d * 1.4426950408889634f);
            esum += e[j];
        }
        const float tot = esum + __shfl_xor_sync(0xffffffffu, esum, 4);
        const float r = rcpa(tot);
#pragma unroll
        for (int j = 0; j < 5; j++) {
            const float cw = e[j] * r;
            sacc[j].x += cw * uh[j].x; sacc[j].y += cw * uh[j].y;
            sacc[j].z += cw * uh[j].z; sacc[j].w += cw * uh[j].w;
        }
    }
    float* so = s_out + b * CD;
#pragma unroll
    for (int j = 0; j < 5; j++) {
        const int cdb = 4 * (sub + 8 * j);
        atomicAdd(&so[cdb + 0], sacc[j].x);
        atomicAdd(&so[cdb + 1], sacc[j].y);
        atomicAdd(&so[cdb + 2], sacc[j].z);
        atomicAdd(&so[cdb + 3], sacc[j].w);
    }
}

// ---------------- launch -----------------------------------------------------
extern "C" void kernel_launch(void* const* d_in, const int* in_sizes, int n_in,
                              void* d_out, int out_size) {
    const float* u = (const float*)d_in[0];
    const float* W = (const float*)d_in[1];
    if (n_in >= 2 && in_sizes[0] == IC * CD * KD) {
        const float* t = u; u = W; W = t;
    }

    cudaFuncSetAttribute(k_uhat, cudaFuncAttributeMaxDynamicSharedMemorySize,
                         K1_SMEM_FLOATS * (int)sizeof(float));

    void* ps;
    cudaGetSymbolAddress(&ps, g_s);
    float* s1 = (float*)ps;
    float* s2 = s1 + B_TOT * CD;
    float* s3 = s2 + B_TOT * CD;

    cudaMemsetAsync(ps, 0, 3 * B_TOT * CD * sizeof(float), 0);

    // 1) u_hat (fp16) + raw sum over i (iter-0 coupling coeffs are exactly 0.1)
    k_uhat<<<dim3(B_TOT / BT, IC / IT), K1_THREADS,
             K1_SMEM_FLOATS * sizeof(float)>>>(u, W);

    // 2) iter-1: v1 = squash(0.1*s1) fused; logits = <uhat, v1>; s2
    k_route<1><<<dim3(B_TOT, NSPL), RT_THREADS>>>(s1, 0.1f, s1, s2);
    // 3) iter-2: vc = v1+v2 fused; logits = <uhat, v1+v2>; s3
    k_route<2><<<dim3(B_TOT, NSPL), RT_THREADS>>>(s1, 0.1f, s2, s3);
    // 4) output v = squash(s3)
    const int sq_blocks = (B_TOT * 10 + 255) / 256;
    k_squash<<<sq_blocks, 256>>>(s3, (float*)d_out, 1.0f);
}